// round 9
// baseline (speedup 1.0000x reference)
#include <cuda_runtime.h>
#include <cuda_bf16.h>
#include <math.h>

#define NN 20000
#define NE 320000
#define HD 512
#define NG 64
#define CAP 64            // direct-indexed CSR capacity per node (Poisson(16): safe)
#define NKC 37            // K-chunks
#define KC16 34           // k16 steps per chunk
#define KCN (KC16 * 16)   // 544 nodes per chunk; 37*544 = 20128 >= 20000
#define NCB 4             // column blocks of 128

// ---------------- device scratch ----------------
// single zero-init region: [w-table NN*32][degree NN][m NG]
__device__ unsigned g_zero[NN * 32 + NN + NG];
#define g_w   (g_zero)
#define g_deg (g_zero + NN * 32)
#define g_m   ((int*)(g_zero + NN * 32 + NN))

__device__ int      g_dstBySrc[NN * CAP];   // direct-indexed CSR (5.1 MB)
__device__ unsigned g_vb[NN * 32];          // v as packed bf16x2 (graphs 2w, 2w+1)
__device__ int      g_scale1[NG];           // n_g + m_g
__device__ int      g_nn[NG];               // n_g
__device__ float    g_part[(size_t)(NKC * NCB) * NG * 128];
__device__ float    g_U[NG * HD], g_P[NG * HD], g_pooled[NG * HD];

__device__ __forceinline__ unsigned pk16(unsigned short lo, unsigned short hi) {
    return (unsigned)lo | ((unsigned)hi << 16);
}

// ---------------- 1. hist + direct CSR fill (fused) ----------------
__global__ void k_hist(const int* __restrict__ src, const int* __restrict__ dst,
                       const int* __restrict__ batch) {
    int e = blockIdx.x * blockDim.x + threadIdx.x;
    if (e < NE) {
        int s = src[e];
        int d = dst[e];
        int gb = batch[d];
        unsigned slot = atomicAdd(&g_deg[s], 1u);
        if (slot < CAP) g_dstBySrc[s * CAP + slot] = d;
        atomicAdd(&g_w[s * 32 + (gb >> 1)], 1u << ((gb & 1) * 16));
        atomicAdd(&g_m[gb], 1);
    }
    if (e < NN) {
        int gb = batch[e];
        atomicAdd(&g_w[e * 32 + (gb >> 1)], 1u << ((gb & 1) * 16));
    }
}

// ---------------- 2. v gather (packed u32 math), output bf16x2 ----------------
__global__ void __launch_bounds__(256) k_vgather() {
    int i = (blockIdx.x * 256 + threadIdx.x) >> 5;
    int lane = threadIdx.x & 31;
    if (i >= NN) return;
    const unsigned* __restrict__ w = g_w;
    unsigned a = w[(size_t)i * 32 + lane];
    unsigned b = 0, c = 0, d = 0;
    int n = g_deg[i]; if (n > CAP) n = CAP;
    const int* __restrict__ lst = g_dstBySrc + (size_t)i * CAP;
    int f = 0;
    for (; f + 4 <= n; f += 4) {
        int d0 = lst[f], d1 = lst[f + 1], d2 = lst[f + 2], d3 = lst[f + 3];
        a += w[(size_t)d0 * 32 + lane];
        b += w[(size_t)d1 * 32 + lane];
        c += w[(size_t)d2 * 32 + lane];
        d += w[(size_t)d3 * 32 + lane];
    }
    for (; f < n; f++) a += w[(size_t)lst[f] * 32 + lane];
    unsigned tot = a + b + c + d;
    float lo = (float)(tot & 0xFFFFu);
    float hi = (float)(tot >> 16);
    unsigned short hl = __bfloat16_as_ushort(__float2bfloat16(lo));
    unsigned short hh = __bfloat16_as_ushort(__float2bfloat16(hi));
    g_vb[(size_t)i * 32 + lane] = pk16(hl, hh);
}

// ---------------- 3. tensor-core U-GEMM (mma.sync m16n8k16 bf16, split-x) ----------------
__global__ void __launch_bounds__(256) k_gemm(const float* __restrict__ x) {
    int kc = blockIdx.x >> 2;
    int cb = blockIdx.x & 3;
    int tid = threadIdx.x;
    int warp = tid >> 5, lane = tid & 31;
    int wm = warp >> 1, wn = warp & 1;
    int t4 = lane & 3, gid = lane >> 2;
    int c2 = t4 * 2;

    __shared__ unsigned short sv[2][16][66];
    __shared__ unsigned short sxh[2][16][136];
    __shared__ unsigned short sxl[2][16][136];

    float acc[8][4];
#pragma unroll
    for (int i = 0; i < 8; i++) {
        acc[i][0] = 0.f; acc[i][1] = 0.f; acc[i][2] = 0.f; acc[i][3] = 0.f;
    }

    int k0 = kc * KCN;
    int xk = tid >> 4;
    int xn = (tid & 15) * 8;
    const float* xbase = x + (size_t)cb * 128 + xn;
    int vrow0 = tid >> 5, vw0 = tid & 31;
    int vrow1 = (tid + 256) >> 5, vw1 = tid & 31;

    float4 xr0, xr1, xp0, xp1;
    unsigned vr0, vr1, vp0, vp1;

    {
        int kk = k0 + xk;
        if (kk < NN) {
            const float4* p = (const float4*)(xbase + (size_t)kk * HD);
            xr0 = p[0]; xr1 = p[1];
        } else { xr0 = make_float4(0.f,0.f,0.f,0.f); xr1 = xr0; }
        int ka = k0 + vrow0, kb = k0 + vrow1;
        vr0 = (ka < NN) ? g_vb[(size_t)ka * 32 + vw0] : 0u;
        vr1 = (kb < NN) ? g_vb[(size_t)kb * 32 + vw1] : 0u;
    }

    for (int t = 0; t < KC16; t++) {
        int buf = t & 1;
        {
            float vals[8] = {xr0.x, xr0.y, xr0.z, xr0.w, xr1.x, xr1.y, xr1.z, xr1.w};
#pragma unroll
            for (int j = 0; j < 8; j++) {
                float v = vals[j];
                __nv_bfloat16 h = __float2bfloat16(v);
                float hf = __bfloat162float(h);
                __nv_bfloat16 l = __float2bfloat16(v - hf);
                sxh[buf][xk][xn + j] = __bfloat16_as_ushort(h);
                sxl[buf][xk][xn + j] = __bfloat16_as_ushort(l);
            }
            *(unsigned*)&sv[buf][vrow0][vw0 * 2] = vr0;
            *(unsigned*)&sv[buf][vrow1][vw1 * 2] = vr1;
        }
        if (t + 1 < KC16) {
            int kk = k0 + (t + 1) * 16 + xk;
            if (kk < NN) {
                const float4* p = (const float4*)(xbase + (size_t)kk * HD);
                xp0 = p[0]; xp1 = p[1];
            } else { xp0 = make_float4(0.f,0.f,0.f,0.f); xp1 = xp0; }
            int ka = k0 + (t + 1) * 16 + vrow0, kb = k0 + (t + 1) * 16 + vrow1;
            vp0 = (ka < NN) ? g_vb[(size_t)ka * 32 + vw0] : 0u;
            vp1 = (kb < NN) ? g_vb[(size_t)kb * 32 + vw1] : 0u;
        }
        __syncthreads();

        int g0 = wm * 16 + gid;
        unsigned a0 = pk16(sv[buf][c2][g0],     sv[buf][c2 + 1][g0]);
        unsigned a1 = pk16(sv[buf][c2][g0 + 8], sv[buf][c2 + 1][g0 + 8]);
        unsigned a2 = pk16(sv[buf][c2 + 8][g0],     sv[buf][c2 + 9][g0]);
        unsigned a3 = pk16(sv[buf][c2 + 8][g0 + 8], sv[buf][c2 + 9][g0 + 8]);

#pragma unroll
        for (int slab = 0; slab < 2; slab++) {
            unsigned short (*sx)[136] = slab ? sxl[buf] : sxh[buf];
#pragma unroll
            for (int tn = 0; tn < 8; tn++) {
                int nn = wn * 64 + tn * 8 + gid;
                unsigned b0 = pk16(sx[c2][nn],     sx[c2 + 1][nn]);
                unsigned b1 = pk16(sx[c2 + 8][nn], sx[c2 + 9][nn]);
                asm volatile(
                    "mma.sync.aligned.m16n8k16.row.col.f32.bf16.bf16.f32 "
                    "{%0,%1,%2,%3}, {%4,%5,%6,%7}, {%8,%9}, {%0,%1,%2,%3};"
                    : "+f"(acc[tn][0]), "+f"(acc[tn][1]), "+f"(acc[tn][2]), "+f"(acc[tn][3])
                    : "r"(a0), "r"(a1), "r"(a2), "r"(a3), "r"(b0), "r"(b1));
            }
        }
        xr0 = xp0; xr1 = xp1; vr0 = vp0; vr1 = vp1;
        __syncthreads();
    }

    float* P = g_part + (size_t)blockIdx.x * NG * 128;
#pragma unroll
    for (int tn = 0; tn < 8; tn++) {
        int c = wn * 64 + tn * 8 + c2;
        int g = wm * 16 + gid;
        *(float2*)&P[g * 128 + c]       = make_float2(acc[tn][0], acc[tn][1]);
        *(float2*)&P[(g + 8) * 128 + c] = make_float2(acc[tn][2], acc[tn][3]);
    }
}

// ---------------- 4. reduce partials -> U (coalesced, 32k threads) + scales ----------------
__device__ __forceinline__ int lbound(const int* a, int n, int v) {
    int lo = 0, hi = n;
    while (lo < hi) { int mid = (lo + hi) >> 1; if (a[mid] < v) lo = mid + 1; else hi = mid; }
    return lo;
}

__global__ void __launch_bounds__(256) k_reduceP(const int* __restrict__ batch) {
    int idx = blockIdx.x * 256 + threadIdx.x;   // 0..32767 = g*512 + c
    int g = idx >> 9;
    int c = idx & 511;
    int cb = c >> 7, cc = c & 127;
    const float* __restrict__ p = g_part + (size_t)cb * (NG * 128) + g * 128 + cc;
    const size_t stride = (size_t)NCB * NG * 128;   // one kc step
    float s0 = 0.f, s1 = 0.f, s2 = 0.f, s3 = 0.f;
    int kc = 0;
    for (; kc + 4 <= NKC; kc += 4) {
        s0 += p[(size_t)(kc + 0) * stride];
        s1 += p[(size_t)(kc + 1) * stride];
        s2 += p[(size_t)(kc + 2) * stride];
        s3 += p[(size_t)(kc + 3) * stride];
    }
    for (; kc < NKC; kc++) s0 += p[(size_t)kc * stride];
    g_U[idx] = (s0 + s1) + (s2 + s3);

    // scales: one thread per graph (block 0 only)
    if (blockIdx.x == 0 && threadIdx.x < NG) {
        int gg = threadIdx.x;
        int lo = lbound(batch, NN, gg);
        int hi = lbound(batch, NN, gg + 1);
        int n = hi - lo;
        g_nn[gg] = n;
        g_scale1[gg] = n + g_m[gg];
    }
}

// ---------------- 5. small GEMM, W read once: out[64,512] = in @ W + scale*bias ----------------
__global__ void __launch_bounds__(256) k_mmT(const float* __restrict__ in,
                                             const float* __restrict__ W,
                                             const float* __restrict__ bias,
                                             const int* __restrict__ scale,
                                             float* __restrict__ out) {
    __shared__ float sW[HD][8];
    int c0 = blockIdx.x * 8;
    int t = threadIdx.x;
    {
        int k = t * 2;
        const float4* p0 = (const float4*)(W + (size_t)k * HD + c0);
        const float4* p1 = (const float4*)(W + (size_t)(k + 1) * HD + c0);
        *(float4*)&sW[k][0] = p0[0];     *(float4*)&sW[k][4] = p0[1];
        *(float4*)&sW[k + 1][0] = p1[0]; *(float4*)&sW[k + 1][4] = p1[1];
    }
    __syncthreads();
    int g = t >> 2, cp = (t & 3) * 2;
    float a0 = 0.f, a1 = 0.f;
    const float* inr = in + (size_t)g * HD;
#pragma unroll 8
    for (int k = 0; k < HD; k++) {
        float a = inr[k];
        a0 += a * sW[k][cp];
        a1 += a * sW[k][cp + 1];
    }
    float sc = (float)scale[g];
    out[(size_t)g * HD + c0 + cp]     = a0 + bias[c0 + cp] * sc;
    out[(size_t)g * HD + c0 + cp + 1] = a1 + bias[c0 + cp + 1] * sc;
}

// ---------------- 6. classifier head ----------------
__global__ void __launch_bounds__(256) k_head(const float* __restrict__ Wc1,
                                              const float* __restrict__ bc1,
                                              const float* __restrict__ Wc2,
                                              const float* __restrict__ bc2,
                                              float* __restrict__ out) {
    int g = blockIdx.x;
    int j = threadIdx.x;
    __shared__ float sp[HD];
    for (int k = j; k < HD; k += 256) sp[k] = g_pooled[g * HD + k];
    __syncthreads();
    float acc = 0.f;
#pragma unroll 8
    for (int k = 0; k < HD; k++) acc += sp[k] * Wc1[k * 256 + j];
    float zj = fmaxf(acc + bc1[j], 0.f) * Wc2[j];
    __shared__ float red[256];
    red[j] = zj;
    __syncthreads();
    for (int ofs = 128; ofs > 0; ofs >>= 1) {
        if (j < ofs) red[j] += red[j + ofs];
        __syncthreads();
    }
    if (j == 0) {
        float s = red[0] + bc2[0];
        out[g] = 1.0f / (1.0f + expf(-s));
    }
}

// ---------------- launch ----------------
extern "C" void kernel_launch(void* const* d_in, const int* in_sizes, int n_in,
                              void* d_out, int out_size) {
    const float* x     = (const float*)d_in[0];
    const int*   ei    = (const int*)d_in[1];
    const int*   batch = (const int*)d_in[2];
    const float* W_g1  = (const float*)d_in[3];
    const float* b_g1  = (const float*)d_in[4];
    const float* W_g2  = (const float*)d_in[5];
    const float* b_g2  = (const float*)d_in[6];
    const float* W_c1  = (const float*)d_in[7];
    const float* b_c1  = (const float*)d_in[8];
    const float* W_c2  = (const float*)d_in[9];
    const float* b_c2  = (const float*)d_in[10];
    float* out = (float*)d_out;

    const int* src = ei;
    const int* dst = ei + NE;

    float *pU, *pP, *pPooled;
    int *pS1, *pNN;
    unsigned* pZero;
    cudaGetSymbolAddress((void**)&pU, g_U);
    cudaGetSymbolAddress((void**)&pP, g_P);
    cudaGetSymbolAddress((void**)&pPooled, g_pooled);
    cudaGetSymbolAddress((void**)&pS1, g_scale1);
    cudaGetSymbolAddress((void**)&pNN, g_nn);
    cudaGetSymbolAddress((void**)&pZero, g_zero);

    cudaMemsetAsync(pZero, 0, sizeof(unsigned) * (NN * 32 + NN + NG));

    k_hist<<<(NE + 255) / 256, 256>>>(src, dst, batch);
    k_vgather<<<(NN * 32 + 255) / 256, 256>>>();
    k_gemm<<<NKC * NCB, 256>>>(x);
    k_reduceP<<<(NG * HD) / 256, 256>>>(batch);
    k_mmT<<<HD / 8, 256>>>(pU, W_g1, b_g1, pS1, pP);
    k_mmT<<<HD / 8, 256>>>(pP, W_g2, b_g2, pNN, pPooled);
    k_head<<<NG, 256>>>(W_c1, b_c1, W_c2, b_c2, out);
}

// round 11
// speedup vs baseline: 1.2876x; 1.2876x over previous
#include <cuda_runtime.h>
#include <cuda_bf16.h>
#include <math.h>

#define NN 20000
#define NE 320000
#define HD 512
#define NG 64
#define CAP 64            // direct-indexed CSR capacity per node (Poisson(16): safe)
#define NKC 37            // K-chunks
#define KC16 34           // k16 steps per chunk
#define KCN (KC16 * 16)   // 544 nodes per chunk; 37*544 = 20128 >= 20000
#define NCB 4             // column blocks of 128
#define RPB 157           // w-table rows per reduce block (128*157 >= 20000)

// ---------------- device scratch ----------------
// single zero-init region: [w-table NN*32][degree NN][wsum 32]
__device__ unsigned g_zero[NN * 32 + NN + 32];
#define g_w    (g_zero)
#define g_deg  (g_zero + NN * 32)
#define g_wsum (g_zero + NN * 32 + NN)

__device__ int      g_dstBySrc[NN * CAP];   // direct-indexed CSR (5.1 MB)
__device__ unsigned g_vb[NN * 32];          // v as packed bf16x2 (graphs 2w, 2w+1)
__device__ int      g_nn[NG];               // n_g
__device__ float    g_part[(size_t)(NKC * NCB) * NG * 128];
__device__ float    g_U[NG * HD], g_P[NG * HD], g_pooled[NG * HD];

__device__ __forceinline__ unsigned pk16(unsigned short lo, unsigned short hi) {
    return (unsigned)lo | ((unsigned)hi << 16);
}

// ---------------- 1. hist + direct CSR fill (fused) ----------------
__global__ void k_hist(const int* __restrict__ src, const int* __restrict__ dst,
                       const int* __restrict__ batch) {
    int e = blockIdx.x * blockDim.x + threadIdx.x;
    if (e < NE) {
        int s = src[e];
        int d = dst[e];
        int gb = batch[d];
        unsigned slot = atomicAdd(&g_deg[s], 1u);
        if (slot < CAP) g_dstBySrc[s * CAP + slot] = d;
        atomicAdd(&g_w[s * 32 + (gb >> 1)], 1u << ((gb & 1) * 16));
    }
    if (e < NN) {
        int gb = batch[e];
        atomicAdd(&g_w[e * 32 + (gb >> 1)], 1u << ((gb & 1) * 16));
    }
}

// ---------------- 2. v gather (packed u32 math), output bf16x2 ----------------
__global__ void __launch_bounds__(256) k_vgather() {
    int i = (blockIdx.x * 256 + threadIdx.x) >> 5;
    int lane = threadIdx.x & 31;
    if (i >= NN) return;
    const unsigned* __restrict__ w = g_w;
    unsigned a = w[(size_t)i * 32 + lane];
    unsigned b = 0, c = 0, d = 0;
    int n = g_deg[i]; if (n > CAP) n = CAP;
    const int* __restrict__ lst = g_dstBySrc + (size_t)i * CAP;
    int f = 0;
    for (; f + 4 <= n; f += 4) {
        int d0 = lst[f], d1 = lst[f + 1], d2 = lst[f + 2], d3 = lst[f + 3];
        a += w[(size_t)d0 * 32 + lane];
        b += w[(size_t)d1 * 32 + lane];
        c += w[(size_t)d2 * 32 + lane];
        d += w[(size_t)d3 * 32 + lane];
    }
    for (; f < n; f++) a += w[(size_t)lst[f] * 32 + lane];
    unsigned tot = a + b + c + d;
    float lo = (float)(tot & 0xFFFFu);
    float hi = (float)(tot >> 16);
    unsigned short hl = __bfloat16_as_ushort(__float2bfloat16(lo));
    unsigned short hh = __bfloat16_as_ushort(__float2bfloat16(hi));
    g_vb[(size_t)i * 32 + lane] = pk16(hl, hh);
}

// ---------------- 3. tensor-core U-GEMM (mma.sync m16n8k16 bf16, split-x) ----------------
__global__ void __launch_bounds__(256) k_gemm(const float* __restrict__ x) {
    int kc = blockIdx.x >> 2;
    int cb = blockIdx.x & 3;
    int tid = threadIdx.x;
    int warp = tid >> 5, lane = tid & 31;
    int wm = warp >> 1, wn = warp & 1;
    int t4 = lane & 3, gid = lane >> 2;
    int c2 = t4 * 2;

    __shared__ unsigned short sv[2][16][66];
    __shared__ unsigned short sxh[2][16][136];
    __shared__ unsigned short sxl[2][16][136];

    float acc[8][4];
#pragma unroll
    for (int i = 0; i < 8; i++) {
        acc[i][0] = 0.f; acc[i][1] = 0.f; acc[i][2] = 0.f; acc[i][3] = 0.f;
    }

    int k0 = kc * KCN;
    int xk = tid >> 4;
    int xn = (tid & 15) * 8;
    const float* xbase = x + (size_t)cb * 128 + xn;
    int vrow0 = tid >> 5, vw0 = tid & 31;
    int vrow1 = (tid + 256) >> 5, vw1 = tid & 31;

    float4 xr0, xr1, xp0, xp1;
    unsigned vr0, vr1, vp0, vp1;

    {
        int kk = k0 + xk;
        if (kk < NN) {
            const float4* p = (const float4*)(xbase + (size_t)kk * HD);
            xr0 = p[0]; xr1 = p[1];
        } else { xr0 = make_float4(0.f,0.f,0.f,0.f); xr1 = xr0; }
        int ka = k0 + vrow0, kb = k0 + vrow1;
        vr0 = (ka < NN) ? g_vb[(size_t)ka * 32 + vw0] : 0u;
        vr1 = (kb < NN) ? g_vb[(size_t)kb * 32 + vw1] : 0u;
    }

    for (int t = 0; t < KC16; t++) {
        int buf = t & 1;
        {
            float vals[8] = {xr0.x, xr0.y, xr0.z, xr0.w, xr1.x, xr1.y, xr1.z, xr1.w};
#pragma unroll
            for (int j = 0; j < 8; j++) {
                float v = vals[j];
                __nv_bfloat16 h = __float2bfloat16(v);
                float hf = __bfloat162float(h);
                __nv_bfloat16 l = __float2bfloat16(v - hf);
                sxh[buf][xk][xn + j] = __bfloat16_as_ushort(h);
                sxl[buf][xk][xn + j] = __bfloat16_as_ushort(l);
            }
            *(unsigned*)&sv[buf][vrow0][vw0 * 2] = vr0;
            *(unsigned*)&sv[buf][vrow1][vw1 * 2] = vr1;
        }
        if (t + 1 < KC16) {
            int kk = k0 + (t + 1) * 16 + xk;
            if (kk < NN) {
                const float4* p = (const float4*)(xbase + (size_t)kk * HD);
                xp0 = p[0]; xp1 = p[1];
            } else { xp0 = make_float4(0.f,0.f,0.f,0.f); xp1 = xp0; }
            int ka = k0 + (t + 1) * 16 + vrow0, kb = k0 + (t + 1) * 16 + vrow1;
            vp0 = (ka < NN) ? g_vb[(size_t)ka * 32 + vw0] : 0u;
            vp1 = (kb < NN) ? g_vb[(size_t)kb * 32 + vw1] : 0u;
        }
        __syncthreads();

        int g0 = wm * 16 + gid;
        unsigned a0 = pk16(sv[buf][c2][g0],     sv[buf][c2 + 1][g0]);
        unsigned a1 = pk16(sv[buf][c2][g0 + 8], sv[buf][c2 + 1][g0 + 8]);
        unsigned a2 = pk16(sv[buf][c2 + 8][g0],     sv[buf][c2 + 9][g0]);
        unsigned a3 = pk16(sv[buf][c2 + 8][g0 + 8], sv[buf][c2 + 9][g0 + 8]);

#pragma unroll
        for (int slab = 0; slab < 2; slab++) {
            unsigned short (*sx)[136] = slab ? sxl[buf] : sxh[buf];
#pragma unroll
            for (int tn = 0; tn < 8; tn++) {
                int nn = wn * 64 + tn * 8 + gid;
                unsigned b0 = pk16(sx[c2][nn],     sx[c2 + 1][nn]);
                unsigned b1 = pk16(sx[c2 + 8][nn], sx[c2 + 9][nn]);
                asm volatile(
                    "mma.sync.aligned.m16n8k16.row.col.f32.bf16.bf16.f32 "
                    "{%0,%1,%2,%3}, {%4,%5,%6,%7}, {%8,%9}, {%0,%1,%2,%3};"
                    : "+f"(acc[tn][0]), "+f"(acc[tn][1]), "+f"(acc[tn][2]), "+f"(acc[tn][3])
                    : "r"(a0), "r"(a1), "r"(a2), "r"(a3), "r"(b0), "r"(b1));
            }
        }
        xr0 = xp0; xr1 = xp1; vr0 = vp0; vr1 = vp1;
        // single sync per step: next iteration writes the other buffer — race-free
    }

    float* P = g_part + (size_t)blockIdx.x * NG * 128;
#pragma unroll
    for (int tn = 0; tn < 8; tn++) {
        int c = wn * 64 + tn * 8 + c2;
        int g = wm * 16 + gid;
        *(float2*)&P[g * 128 + c]       = make_float2(acc[tn][0], acc[tn][1]);
        *(float2*)&P[(g + 8) * 128 + c] = make_float2(acc[tn][2], acc[tn][3]);
    }
}

// ---------------- 4. reduce partials -> U + coalesced w column-sum + n_g ----------------
__device__ __forceinline__ int lbound(const int* a, int n, int v) {
    int lo = 0, hi = n;
    while (lo < hi) { int mid = (lo + hi) >> 1; if (a[mid] < v) lo = mid + 1; else hi = mid; }
    return lo;
}

__global__ void __launch_bounds__(256) k_reduceP(const int* __restrict__ batch) {
    int idx = blockIdx.x * 256 + threadIdx.x;   // 0..32767 = g*512 + c
    {   // U reduce (coalesced over kc)
        int g = idx >> 9;
        int c = idx & 511;
        int cb = c >> 7, cc = c & 127;
        const float* __restrict__ p = g_part + (size_t)cb * (NG * 128) + g * 128 + cc;
        const size_t stride = (size_t)NCB * NG * 128;
        float s0 = 0.f, s1 = 0.f, s2 = 0.f, s3 = 0.f;
        int kc = 0;
        for (; kc + 4 <= NKC; kc += 4) {
            s0 += p[(size_t)(kc + 0) * stride];
            s1 += p[(size_t)(kc + 1) * stride];
            s2 += p[(size_t)(kc + 2) * stride];
            s3 += p[(size_t)(kc + 3) * stride];
        }
        for (; kc < NKC; kc++) s0 += p[(size_t)kc * stride];
        g_U[idx] = (s0 + s1) + (s2 + s3);
    }

    // packed column-sum of w over this block's row slice (coalesced)
    {
        int r0 = blockIdx.x * RPB;
        int r1 = r0 + RPB; if (r1 > NN) r1 = NN;
        int word = threadIdx.x & 31, rsub = threadIdx.x >> 5;   // 8 row-groups
        unsigned accp = 0;
        for (int r = r0 + rsub; r < r1; r += 8)
            accp += g_w[(size_t)r * 32 + word];                 // fields <= ~10k, no overflow
        __shared__ unsigned sw[8][32];
        sw[rsub][word] = accp;
        __syncthreads();
        if (threadIdx.x < 32) {
            unsigned s = 0;
#pragma unroll
            for (int j = 0; j < 8; j++) s += sw[j][threadIdx.x];
            atomicAdd(&g_wsum[threadIdx.x], s);
        }
    }

    // n_g via binary search on sorted batch (block 0, lanes 128..191)
    if (blockIdx.x == 0 && threadIdx.x >= 128 && threadIdx.x < 128 + NG) {
        int gg = threadIdx.x - 128;
        int lo = lbound(batch, NN, gg);
        int hi = lbound(batch, NN, gg + 1);
        g_nn[gg] = hi - lo;
    }
}

// ---------------- 5. small GEMM, W read once: out[64,512] = in @ W + scale*bias ----------------
// scale_pk (packed 16-bit fields) takes precedence over scale_int
__global__ void __launch_bounds__(256) k_mmT(const float* __restrict__ in,
                                             const float* __restrict__ W,
                                             const float* __restrict__ bias,
                                             const unsigned* __restrict__ scale_pk,
                                             const int* __restrict__ scale_int,
                                             float* __restrict__ out) {
    __shared__ float sW[HD][8];
    int c0 = blockIdx.x * 8;
    int t = threadIdx.x;
    {
        int k = t * 2;
        const float4* p0 = (const float4*)(W + (size_t)k * HD + c0);
        const float4* p1 = (const float4*)(W + (size_t)(k + 1) * HD + c0);
        *(float4*)&sW[k][0] = p0[0];     *(float4*)&sW[k][4] = p0[1];
        *(float4*)&sW[k + 1][0] = p1[0]; *(float4*)&sW[k + 1][4] = p1[1];
    }
    __syncthreads();
    int g = t >> 2, cp = (t & 3) * 2;
    float a0 = 0.f, a1 = 0.f;
    const float* inr = in + (size_t)g * HD;
#pragma unroll 8
    for (int k = 0; k < HD; k++) {
        float a = inr[k];
        a0 += a * sW[k][cp];
        a1 += a * sW[k][cp + 1];
    }
    float sc = scale_pk ? (float)((scale_pk[g >> 1] >> ((g & 1) * 16)) & 0xFFFFu)
                        : (float)scale_int[g];
    out[(size_t)g * HD + c0 + cp]     = a0 + bias[c0 + cp] * sc;
    out[(size_t)g * HD + c0 + cp + 1] = a1 + bias[c0 + cp + 1] * sc;
}

// ---------------- 6. classifier head ----------------
__global__ void __launch_bounds__(256) k_head(const float* __restrict__ Wc1,
                                              const float* __restrict__ bc1,
                                              const float* __restrict__ Wc2,
                                              const float* __restrict__ bc2,
                                              float* __restrict__ out) {
    int g = blockIdx.x;
    int j = threadIdx.x;
    __shared__ float sp[HD];
    for (int k = j; k < HD; k += 256) sp[k] = g_pooled[g * HD + k];
    __syncthreads();
    float acc = 0.f;
#pragma unroll 8
    for (int k = 0; k < HD; k++) acc += sp[k] * Wc1[k * 256 + j];
    float zj = fmaxf(acc + bc1[j], 0.f) * Wc2[j];
    __shared__ float red[256];
    red[j] = zj;
    __syncthreads();
    for (int ofs = 128; ofs > 0; ofs >>= 1) {
        if (j < ofs) red[j] += red[j + ofs];
        __syncthreads();
    }
    if (j == 0) {
        float s = red[0] + bc2[0];
        out[g] = 1.0f / (1.0f + expf(-s));
    }
}

// ---------------- launch ----------------
extern "C" void kernel_launch(void* const* d_in, const int* in_sizes, int n_in,
                              void* d_out, int out_size) {
    const float* x     = (const float*)d_in[0];
    const int*   ei    = (const int*)d_in[1];
    const int*   batch = (const int*)d_in[2];
    const float* W_g1  = (const float*)d_in[3];
    const float* b_g1  = (const float*)d_in[4];
    const float* W_g2  = (const float*)d_in[5];
    const float* b_g2  = (const float*)d_in[6];
    const float* W_c1  = (const float*)d_in[7];
    const float* b_c1  = (const float*)d_in[8];
    const float* W_c2  = (const float*)d_in[9];
    const float* b_c2  = (const float*)d_in[10];
    float* out = (float*)d_out;

    const int* src = ei;
    const int* dst = ei + NE;

    float *pU, *pP, *pPooled;
    int *pNN;
    unsigned *pZero, *pWsum;
    cudaGetSymbolAddress((void**)&pU, g_U);
    cudaGetSymbolAddress((void**)&pP, g_P);
    cudaGetSymbolAddress((void**)&pPooled, g_pooled);
    cudaGetSymbolAddress((void**)&pNN, g_nn);
    cudaGetSymbolAddress((void**)&pZero, g_zero);
    pWsum = pZero + NN * 32 + NN;

    cudaMemsetAsync(pZero, 0, sizeof(unsigned) * (NN * 32 + NN + 32));

    k_hist<<<(NE + 255) / 256, 256>>>(src, dst, batch);
    k_vgather<<<(NN * 32 + 255) / 256, 256>>>();
    k_gemm<<<NKC * NCB, 256>>>(x);
    k_reduceP<<<(NG * HD) / 256, 256>>>(batch);
    k_mmT<<<HD / 8, 256>>>(pU, W_g1, b_g1, pWsum, (const int*)nullptr, pP);
    k_mmT<<<HD / 8, 256>>>(pP, W_g2, b_g2, (const unsigned*)nullptr, pNN, pPooled);
    k_head<<<NG, 256>>>(W_c1, b_c1, W_c2, b_c2, out);
}